// round 15
// baseline (speedup 1.0000x reference)
#include <cuda_runtime.h>

#define NN 50000
#define NE 800000
#define FD 64
#define GROUP 128          // nodes per block-group (8 per warp)
#define NPW 8              // nodes per warp

// ---------------- scratch (static device globals; no runtime alloc) ----------------
// NOTE: g_deg/g_cnt/g_total are zero at module load and re-zeroed by k_final's
// tail each run, so no separate zeroing kernel is needed (deterministic).
__device__ float g_deg[NN];
__device__ float g_dinv[NN];
__device__ int   g_cnt[NN];
__device__ __align__(16) int2 g_span[NN];  // (off, end) per node
__device__ int   g_cur[NN];
__device__ int   g_total;
__device__ __align__(16) int2  g_edge[NE];          // (src, weight-bits) bucketed by dst
__device__ __align__(16) float g_tx1[NN * FD];
__device__ __align__(16) float g_s2[NN * FD];
__device__ __align__(16) float g_wc[7 * FD * FD];   // combined weights, [mat][k][f]
__device__ float g_bias[3 * FD];                    // bz, bh, blin

typedef unsigned long long ull;

// ---------------- f32x2 packed helpers (sm_103a dual-fp32 datapath) ----------------
__device__ __forceinline__ ull dup2(float a) {
    ull r;
    asm("mov.b64 %0, {%1, %1};" : "=l"(r) : "f"(a));
    return r;
}
__device__ __forceinline__ void fma2(ull& d, ull a, ull b) {
    asm("fma.rn.f32x2 %0, %1, %2, %0;" : "+l"(d) : "l"(a), "l"(b));
}
__device__ __forceinline__ void unpk2(ull v, float& x, float& y) {
    asm("mov.b64 {%0, %1}, %2;" : "=f"(x), "=f"(y) : "l"(v));
}

// ---------------- CSR build ----------------
// 4 edges per thread, vector loads, fire-and-forget REDs (measured-best config)
__global__ void k_hist(const int* __restrict__ src, const int* __restrict__ dst,
                       const float* __restrict__ ew) {
    int idx = blockIdx.x * blockDim.x + threadIdx.x;
    if (idx * 4 >= NE) return;
    int4   s4 = reinterpret_cast<const int4*>(src)[idx];
    int4   d4 = reinterpret_cast<const int4*>(dst)[idx];
    float4 w4 = reinterpret_cast<const float4*>(ew)[idx];
    atomicAdd(&g_deg[s4.x], w4.x); atomicAdd(&g_cnt[d4.x], 1);
    atomicAdd(&g_deg[s4.y], w4.y); atomicAdd(&g_cnt[d4.y], 1);
    atomicAdd(&g_deg[s4.z], w4.z); atomicAdd(&g_cnt[d4.z], 1);
    atomicAdd(&g_deg[s4.w], w4.w); atomicAdd(&g_cnt[d4.w], 1);
}

// dinv + bucket allocation (warp-aggregated bump allocator, NO prefix scan)
// + weight combining + bias combining
__global__ void k_prep(const float* __restrict__ Wxz, const float* __restrict__ bxz,
                       const float* __restrict__ bhz,
                       const float* __restrict__ Wxh, const float* __restrict__ bxh,
                       const float* __restrict__ bhh,
                       const float* __restrict__ Wlin, const float* __restrict__ blin) {
    int i = blockIdx.x * blockDim.x + threadIdx.x;
    int lane = threadIdx.x & 31;

    {   // bucket allocation: warp-scan counts, one atomic per warp
        int c = (i < NN) ? g_cnt[i] : 0;
        int scan = c;
        #pragma unroll
        for (int d = 1; d < 32; d <<= 1) {
            int v = __shfl_up_sync(0xFFFFFFFFu, scan, d);
            if (lane >= d) scan += v;
        }
        int warpsum = __shfl_sync(0xFFFFFFFFu, scan, 31);
        int base = 0;
        if (lane == 31 && warpsum > 0) base = atomicAdd(&g_total, warpsum);
        base = __shfl_sync(0xFFFFFFFFu, base, 31);
        if (i < NN) {
            int off = base + scan - c;
            g_span[i] = make_int2(off, off + c);
            g_cur[i] = off;
            float dg = g_deg[i];
            g_dinv[i] = (dg > 0.f) ? rsqrtf(dg) : 0.f;
        }
    }

    if (i < FD * FD) {
        // Tx2 = 2*S2 - Tx0  =>  fold into W0' = W0 - W2, W2' = 2*W2
        g_wc[0 * 4096 + i] = Wxz[i] - Wxz[2 * 4096 + i];
        g_wc[1 * 4096 + i] = Wxz[4096 + i];
        g_wc[2 * 4096 + i] = 2.f * Wxz[2 * 4096 + i];
        g_wc[3 * 4096 + i] = Wxh[i] - Wxh[2 * 4096 + i];
        g_wc[4 * 4096 + i] = Wxh[4096 + i];
        g_wc[5 * 4096 + i] = 2.f * Wxh[2 * 4096 + i];
        g_wc[6 * 4096 + i] = Wlin[i];
    }
    if (i < FD) {
        g_bias[i]          = bxz[i] + bhz[i];   // H0=0 => cheb(H0)=b_hz
        g_bias[FD + i]     = bxh[i] + bhh[i];
        g_bias[2 * FD + i] = blin[i];
    }
}

// 4 edges per thread, vector loads, independent atomic->store chains (MLP 4)
__global__ void k_permute(const int* __restrict__ src, const int* __restrict__ dst,
                          const float* __restrict__ ew) {
    int idx = blockIdx.x * blockDim.x + threadIdx.x;
    if (idx * 4 >= NE) return;
    int4   s4 = reinterpret_cast<const int4*>(src)[idx];
    int4   d4 = reinterpret_cast<const int4*>(dst)[idx];
    float4 w4 = reinterpret_cast<const float4*>(ew)[idx];
    float c0 = -w4.x * g_dinv[s4.x] * g_dinv[d4.x];
    float c1 = -w4.y * g_dinv[s4.y] * g_dinv[d4.y];
    float c2 = -w4.z * g_dinv[s4.z] * g_dinv[d4.z];
    float c3 = -w4.w * g_dinv[s4.w] * g_dinv[d4.w];
    int p0 = atomicAdd(&g_cur[d4.x], 1);
    int p1 = atomicAdd(&g_cur[d4.y], 1);
    int p2 = atomicAdd(&g_cur[d4.z], 1);
    int p3 = atomicAdd(&g_cur[d4.w], 1);
    g_edge[p0] = make_int2(s4.x, __float_as_int(c0));
    g_edge[p1] = make_int2(s4.y, __float_as_int(c1));
    g_edge[p2] = make_int2(s4.z, __float_as_int(c2));
    g_edge[p3] = make_int2(s4.w, __float_as_int(c3));
}

// ---------------- gather: ONE WARP per dst node, 8 edges/warp-iter ----------------
// lanes 0-15 = half 0, 16-31 = half 1; each half owns 4 independent FMA chains.
// cross-half combine via shfl_xor(16). Dense contiguous edge buckets (g_span).
__device__ __forceinline__ void gather_body(const float4* __restrict__ in4,
                                            float4* __restrict__ out4) {
    int w = (blockIdx.x * blockDim.x + threadIdx.x) >> 5;
    if (w >= NN) return;
    int lane = threadIdx.x & 31;
    int half = lane >> 4, qlane = lane & 15;
    int2 span = g_span[w];
    int beg = span.x, end = span.y;

    float4 a0 = make_float4(0.f, 0.f, 0.f, 0.f);
    float4 a1 = a0, a2 = a0, a3 = a0;
    int i = beg;
    // 8 edges per warp-iteration (4 per half -> MLP 4 per half-lane)
    for (; i + 7 < end; i += 8) {
        int2 e0 = g_edge[i + half];
        int2 e1 = g_edge[i + 2 + half];
        int2 e2 = g_edge[i + 4 + half];
        int2 e3 = g_edge[i + 6 + half];
        float4 v0 = in4[e0.x * 16 + qlane];
        float4 v1 = in4[e1.x * 16 + qlane];
        float4 v2 = in4[e2.x * 16 + qlane];
        float4 v3 = in4[e3.x * 16 + qlane];
        float w0 = __int_as_float(e0.y), w1 = __int_as_float(e1.y);
        float w2 = __int_as_float(e2.y), w3 = __int_as_float(e3.y);
        a0.x = fmaf(w0, v0.x, a0.x); a0.y = fmaf(w0, v0.y, a0.y);
        a0.z = fmaf(w0, v0.z, a0.z); a0.w = fmaf(w0, v0.w, a0.w);
        a1.x = fmaf(w1, v1.x, a1.x); a1.y = fmaf(w1, v1.y, a1.y);
        a1.z = fmaf(w1, v1.z, a1.z); a1.w = fmaf(w1, v1.w, a1.w);
        a2.x = fmaf(w2, v2.x, a2.x); a2.y = fmaf(w2, v2.y, a2.y);
        a2.z = fmaf(w2, v2.z, a2.z); a2.w = fmaf(w2, v2.w, a2.w);
        a3.x = fmaf(w3, v3.x, a3.x); a3.y = fmaf(w3, v3.y, a3.y);
        a3.z = fmaf(w3, v3.z, a3.z); a3.w = fmaf(w3, v3.w, a3.w);
    }
    // pair tail: 2 edges per iter (one per half)
    for (; i + 1 < end; i += 2) {
        int2 e0 = g_edge[i + half];
        float4 v0 = in4[e0.x * 16 + qlane];
        float w0 = __int_as_float(e0.y);
        a0.x = fmaf(w0, v0.x, a0.x); a0.y = fmaf(w0, v0.y, a0.y);
        a0.z = fmaf(w0, v0.z, a0.z); a0.w = fmaf(w0, v0.w, a0.w);
    }
    // last lone edge: half 0 only
    if (i < end && half == 0) {
        int2 e0 = g_edge[i];
        float4 v0 = in4[e0.x * 16 + qlane];
        float w0 = __int_as_float(e0.y);
        a0.x = fmaf(w0, v0.x, a0.x); a0.y = fmaf(w0, v0.y, a0.y);
        a0.z = fmaf(w0, v0.z, a0.z); a0.w = fmaf(w0, v0.w, a0.w);
    }
    a0.x += a1.x + a2.x + a3.x;
    a0.y += a1.y + a2.y + a3.y;
    a0.z += a1.z + a2.z + a3.z;
    a0.w += a1.w + a2.w + a3.w;
    // combine halves
    a0.x += __shfl_xor_sync(0xFFFFFFFFu, a0.x, 16);
    a0.y += __shfl_xor_sync(0xFFFFFFFFu, a0.y, 16);
    a0.z += __shfl_xor_sync(0xFFFFFFFFu, a0.z, 16);
    a0.w += __shfl_xor_sync(0xFFFFFFFFu, a0.w, 16);
    if (half == 0) out4[w * 16 + qlane] = a0;
}

__global__ void k_gather1(const float* __restrict__ x) {
    gather_body(reinterpret_cast<const float4*>(x),
                reinterpret_cast<float4*>(g_tx1));
}

__global__ void k_gather2() {
    gather_body(reinterpret_cast<const float4*>(g_tx1),
                reinterpret_cast<float4*>(g_s2));
}

// ---------------- fused dense kernel: 128 nodes/group, 8 nodes/warp --------------
// H overlays the sTx region (freed after mainloop; sync before overlay writes).
#define SMEM_FLOATS (7 * 4096 + 192 + GROUP * 192)

__global__ void __launch_bounds__(512, 1)
k_final(const float* __restrict__ x, float* __restrict__ out) {
    extern __shared__ float sm[];
    float* sW  = sm;                   // 7*4096
    float* sB  = sW + 7 * 4096;       // 192
    float* sTx = sB + 192;            // GROUP nodes * (Tx0|Tx1|S2) * 64
    float* sH  = sTx;                 // overlay: GROUP*64 after mainloop

    const int tid = threadIdx.x;
    for (int i = tid; i < 7 * 4096; i += 512) sW[i] = g_wc[i];
    for (int i = tid; i < 192; i += 512) sB[i] = g_bias[i];

    const int warp = tid >> 5, lane = tid & 31;
    const int f = lane * 2;
    const int ngroups = (NN + GROUP - 1) / GROUP;

    for (int g = blockIdx.x; g < ngroups; g += gridDim.x) {
        const int base = g * GROUP;
        for (int i = tid; i < GROUP * 16; i += 512) {
            int node = i >> 4, q = i & 15;
            int n = base + node;
            float4 a, b, c;
            if (n < NN) {
                a = reinterpret_cast<const float4*>(x)[n * 16 + q];
                b = reinterpret_cast<const float4*>(g_tx1)[n * 16 + q];
                c = reinterpret_cast<const float4*>(g_s2)[n * 16 + q];
            } else {
                a = make_float4(0.f, 0.f, 0.f, 0.f); b = a; c = a;
            }
            reinterpret_cast<float4*>(sTx)[node * 48 + q]      = a;
            reinterpret_cast<float4*>(sTx)[node * 48 + 16 + q] = b;
            reinterpret_cast<float4*>(sTx)[node * 48 + 32 + q] = c;
        }
        __syncthreads();

        ull az[NPW], ah[NPW];
        {
            ull bz = *(const ull*)&sB[f];
            ull bh = *(const ull*)&sB[64 + f];
            #pragma unroll
            for (int j = 0; j < NPW; j++) { az[j] = bz; ah[j] = bh; }
        }
        const float* t = sTx + (warp * NPW) * 192;

        // mainloop: one activation matrix at a time per k4 block (bounded liveness)
        for (int k4 = 0; k4 < 64; k4 += 4) {
            #pragma unroll
            for (int m = 0; m < 3; m++) {
                ull wz[4], wh[4];
                #pragma unroll
                for (int kk = 0; kk < 4; kk++) {
                    wz[kk] = *(const ull*)&sW[m * 4096 + (k4 + kk) * 64 + f];
                    wh[kk] = *(const ull*)&sW[(m + 3) * 4096 + (k4 + kk) * 64 + f];
                }
                float4 Am[NPW];
                #pragma unroll
                for (int j = 0; j < NPW; j++)
                    Am[j] = *(const float4*)&t[j * 192 + m * 64 + k4];
                #pragma unroll
                for (int kk = 0; kk < 4; kk++) {
                    #pragma unroll
                    for (int j = 0; j < NPW; j++) {
                        const float* pa = (const float*)&Am[j];
                        ull a = dup2(pa[kk]);
                        fma2(az[j], a, wz[kk]);
                        fma2(ah[j], a, wh[kk]);
                    }
                }
            }
        }

        // gates into registers
        float Hx[NPW], Hy[NPW];
        #pragma unroll
        for (int j = 0; j < NPW; j++) {
            float azx, azy, ahx, ahy;
            unpk2(az[j], azx, azy);
            unpk2(ah[j], ahx, ahy);
            float zx = 1.f / (1.f + __expf(-azx));
            float zy = 1.f / (1.f + __expf(-azy));
            float hx = 1.f - 2.f / (__expf(2.f * ahx) + 1.f);
            float hy = 1.f - 2.f / (__expf(2.f * ahy) + 1.f);
            Hx[j] = fmaxf((1.f - zx) * hx, 0.f);
            Hy[j] = fmaxf((1.f - zy) * hy, 0.f);
        }
        __syncthreads();   // ALL warps done reading sTx before H overlay

        #pragma unroll
        for (int j = 0; j < NPW; j++) {
            int node = warp * NPW + j;
            sH[node * 64 + f]     = Hx[j];
            sH[node * 64 + f + 1] = Hy[j];
        }
        // each warp reads only its own nodes' H -> no sync needed

        ull o[NPW];
        {
            ull bl = *(const ull*)&sB[128 + f];
            #pragma unroll
            for (int j = 0; j < NPW; j++) o[j] = bl;
        }
        for (int k4 = 0; k4 < 64; k4 += 4) {
            ull wl[4];
            #pragma unroll
            for (int kk = 0; kk < 4; kk++)
                wl[kk] = *(const ull*)&sW[6 * 4096 + (k4 + kk) * 64 + f];
            float4 Hv[NPW];
            #pragma unroll
            for (int j = 0; j < NPW; j++)
                Hv[j] = *(const float4*)&sH[(warp * NPW + j) * 64 + k4];
            #pragma unroll
            for (int kk = 0; kk < 4; kk++) {
                #pragma unroll
                for (int j = 0; j < NPW; j++) {
                    const float* ph = (const float*)&Hv[j];
                    fma2(o[j], dup2(ph[kk]), wl[kk]);
                }
            }
        }
        #pragma unroll
        for (int j = 0; j < NPW; j++) {
            int n = base + warp * NPW + j;
            if (n < NN) {
                float ox, oy;
                unpk2(o[j], ox, oy);
                *(float2*)&out[n * 64 + f] = make_float2(ox, oy);
            }
        }
        __syncthreads();
    }

    // tail: restore zeroed state for the next invocation (replaces k_zero kernel)
    for (int i = blockIdx.x * 512 + tid; i < NN; i += gridDim.x * 512) {
        g_deg[i] = 0.f;
        g_cnt[i] = 0;
    }
    if (blockIdx.x == 0 && tid == 0) g_total = 0;
}

// ---------------- launch ----------------
extern "C" void kernel_launch(void* const* d_in, const int* in_sizes, int n_in,
                              void* d_out, int out_size) {
    const float* x    = (const float*)d_in[0];
    const int*   ei   = (const int*)d_in[1];
    const float* ew   = (const float*)d_in[2];
    const float* Wxz  = (const float*)d_in[3];
    const float* bxz  = (const float*)d_in[4];
    const float* bhz  = (const float*)d_in[6];   // W_hz unused (H0 = 0)
    const float* Wxh  = (const float*)d_in[11];
    const float* bxh  = (const float*)d_in[12];
    const float* bhh  = (const float*)d_in[14];  // W_hh unused
    const float* Wlin = (const float*)d_in[15];
    const float* blin = (const float*)d_in[16];
    float* out = (float*)d_out;

    const int* src = ei;
    const int* dst = ei + NE;

    cudaFuncSetAttribute(k_final, cudaFuncAttributeMaxDynamicSharedMemorySize,
                         SMEM_FLOATS * (int)sizeof(float));

    k_hist<<<(NE / 4 + 255) / 256, 256>>>(src, dst, ew);
    k_prep<<<(NN + 255) / 256, 256>>>(Wxz, bxz, bhz, Wxh, bxh, bhh, Wlin, blin);
    k_permute<<<(NE / 4 + 255) / 256, 256>>>(src, dst, ew);
    k_gather1<<<(NN * 32 + 255) / 256, 256>>>(x);
    k_gather2<<<(NN * 32 + 255) / 256, 256>>>();
    k_final<<<148, 512, SMEM_FLOATS * (int)sizeof(float)>>>(x, out);
}

// round 16
// speedup vs baseline: 1.0816x; 1.0816x over previous
#include <cuda_runtime.h>

#define NN 50000
#define NE 800000
#define FD 64
#define GROUP 128          // nodes per block-group (8 per warp)
#define NPW 8              // nodes per warp

// ---------------- scratch (static device globals; no runtime alloc) ----------------
// NOTE: g_deg/g_cnt/g_total are zero at module load and re-zeroed by k_final's
// tail each run, so no separate zeroing kernel is needed (deterministic).
__device__ float g_deg[NN];
__device__ float g_dinv[NN];
__device__ int   g_cnt[NN];
__device__ __align__(16) int2 g_span[NN];  // (off, end) per node
__device__ int   g_cur[NN];
__device__ int   g_total;
__device__ __align__(16) int2  g_edge[NE];          // (src, weight-bits) bucketed by dst
__device__ __align__(16) float g_tx1[NN * FD];
__device__ __align__(16) float g_s2[NN * FD];
__device__ __align__(16) float g_wc[7 * FD * FD];   // combined weights, [mat][k][f]
__device__ float g_bias[3 * FD];                    // bz, bh, blin

typedef unsigned long long ull;

// ---------------- f32x2 packed helpers (sm_103a dual-fp32 datapath) ----------------
__device__ __forceinline__ ull dup2(float a) {
    ull r;
    asm("mov.b64 %0, {%1, %1};" : "=l"(r) : "f"(a));
    return r;
}
__device__ __forceinline__ void fma2(ull& d, ull a, ull b) {
    asm("fma.rn.f32x2 %0, %1, %2, %0;" : "+l"(d) : "l"(a), "l"(b));
}
__device__ __forceinline__ void unpk2(ull v, float& x, float& y) {
    asm("mov.b64 {%0, %1}, %2;" : "=f"(x), "=f"(y) : "l"(v));
}

// ---------------- CSR build ----------------
// 4 edges per thread, vector loads, fire-and-forget REDs (measured-best config)
__global__ void k_hist(const int* __restrict__ src, const int* __restrict__ dst,
                       const float* __restrict__ ew) {
    int idx = blockIdx.x * blockDim.x + threadIdx.x;
    if (idx * 4 >= NE) return;
    int4   s4 = reinterpret_cast<const int4*>(src)[idx];
    int4   d4 = reinterpret_cast<const int4*>(dst)[idx];
    float4 w4 = reinterpret_cast<const float4*>(ew)[idx];
    atomicAdd(&g_deg[s4.x], w4.x); atomicAdd(&g_cnt[d4.x], 1);
    atomicAdd(&g_deg[s4.y], w4.y); atomicAdd(&g_cnt[d4.y], 1);
    atomicAdd(&g_deg[s4.z], w4.z); atomicAdd(&g_cnt[d4.z], 1);
    atomicAdd(&g_deg[s4.w], w4.w); atomicAdd(&g_cnt[d4.w], 1);
}

// dinv + bucket allocation (warp-aggregated bump allocator, NO prefix scan)
// + weight combining + bias combining
__global__ void k_prep(const float* __restrict__ Wxz, const float* __restrict__ bxz,
                       const float* __restrict__ bhz,
                       const float* __restrict__ Wxh, const float* __restrict__ bxh,
                       const float* __restrict__ bhh,
                       const float* __restrict__ Wlin, const float* __restrict__ blin) {
    int i = blockIdx.x * blockDim.x + threadIdx.x;
    int lane = threadIdx.x & 31;

    {   // bucket allocation: warp-scan counts, one atomic per warp
        int c = (i < NN) ? g_cnt[i] : 0;
        int scan = c;
        #pragma unroll
        for (int d = 1; d < 32; d <<= 1) {
            int v = __shfl_up_sync(0xFFFFFFFFu, scan, d);
            if (lane >= d) scan += v;
        }
        int warpsum = __shfl_sync(0xFFFFFFFFu, scan, 31);
        int base = 0;
        if (lane == 31 && warpsum > 0) base = atomicAdd(&g_total, warpsum);
        base = __shfl_sync(0xFFFFFFFFu, base, 31);
        if (i < NN) {
            int off = base + scan - c;
            g_span[i] = make_int2(off, off + c);
            g_cur[i] = off;
            float dg = g_deg[i];
            g_dinv[i] = (dg > 0.f) ? rsqrtf(dg) : 0.f;
        }
    }

    if (i < FD * FD) {
        // Tx2 = 2*S2 - Tx0  =>  fold into W0' = W0 - W2, W2' = 2*W2
        g_wc[0 * 4096 + i] = Wxz[i] - Wxz[2 * 4096 + i];
        g_wc[1 * 4096 + i] = Wxz[4096 + i];
        g_wc[2 * 4096 + i] = 2.f * Wxz[2 * 4096 + i];
        g_wc[3 * 4096 + i] = Wxh[i] - Wxh[2 * 4096 + i];
        g_wc[4 * 4096 + i] = Wxh[4096 + i];
        g_wc[5 * 4096 + i] = 2.f * Wxh[2 * 4096 + i];
        g_wc[6 * 4096 + i] = Wlin[i];
    }
    if (i < FD) {
        g_bias[i]          = bxz[i] + bhz[i];   // H0=0 => cheb(H0)=b_hz
        g_bias[FD + i]     = bxh[i] + bhh[i];
        g_bias[2 * FD + i] = blin[i];
    }
}

// 4 edges per thread, vector loads, independent atomic->store chains (MLP 4)
// edge records stored with streaming hint (write-once, read-twice-later)
__global__ void k_permute(const int* __restrict__ src, const int* __restrict__ dst,
                          const float* __restrict__ ew) {
    int idx = blockIdx.x * blockDim.x + threadIdx.x;
    if (idx * 4 >= NE) return;
    int4   s4 = reinterpret_cast<const int4*>(src)[idx];
    int4   d4 = reinterpret_cast<const int4*>(dst)[idx];
    float4 w4 = reinterpret_cast<const float4*>(ew)[idx];
    float c0 = -w4.x * g_dinv[s4.x] * g_dinv[d4.x];
    float c1 = -w4.y * g_dinv[s4.y] * g_dinv[d4.y];
    float c2 = -w4.z * g_dinv[s4.z] * g_dinv[d4.z];
    float c3 = -w4.w * g_dinv[s4.w] * g_dinv[d4.w];
    int p0 = atomicAdd(&g_cur[d4.x], 1);
    int p1 = atomicAdd(&g_cur[d4.y], 1);
    int p2 = atomicAdd(&g_cur[d4.z], 1);
    int p3 = atomicAdd(&g_cur[d4.w], 1);
    __stcs(&g_edge[p0], make_int2(s4.x, __float_as_int(c0)));
    __stcs(&g_edge[p1], make_int2(s4.y, __float_as_int(c1)));
    __stcs(&g_edge[p2], make_int2(s4.z, __float_as_int(c2)));
    __stcs(&g_edge[p3], make_int2(s4.w, __float_as_int(c3)));
}

// ---------------- gather: ONE WARP per dst node, 4 edges/warp-iter ----------------
// lanes 0-15 = half 0, 16-31 = half 1 (uniform loop bounds, no divergence);
// cross-half combine via shfl_xor(16). Edge loads use streaming hint (read-once),
// keeping L2 capacity for the reused feature rows.
__device__ __forceinline__ void gather_body(const float4* __restrict__ in4,
                                            float4* __restrict__ out4) {
    int w = (blockIdx.x * blockDim.x + threadIdx.x) >> 5;
    if (w >= NN) return;
    int lane = threadIdx.x & 31;
    int half = lane >> 4, qlane = lane & 15;
    int2 span = g_span[w];
    int beg = span.x, end = span.y;

    float4 a0 = make_float4(0.f, 0.f, 0.f, 0.f);
    float4 a1 = a0;
    int i = beg;
    // 4 edges per warp-iteration: half handles i+half and i+2+half
    for (; i + 3 < end; i += 4) {
        int2 e0 = __ldcs(&g_edge[i + half]);
        int2 e1 = __ldcs(&g_edge[i + 2 + half]);
        float4 v0 = in4[e0.x * 16 + qlane];
        float4 v1 = in4[e1.x * 16 + qlane];
        float w0 = __int_as_float(e0.y), w1 = __int_as_float(e1.y);
        a0.x = fmaf(w0, v0.x, a0.x); a0.y = fmaf(w0, v0.y, a0.y);
        a0.z = fmaf(w0, v0.z, a0.z); a0.w = fmaf(w0, v0.w, a0.w);
        a1.x = fmaf(w1, v1.x, a1.x); a1.y = fmaf(w1, v1.y, a1.y);
        a1.z = fmaf(w1, v1.z, a1.z); a1.w = fmaf(w1, v1.w, a1.w);
    }
    // tail (0-3 edges), predicated per half
    if (i + half < end) {
        int2 e0 = __ldcs(&g_edge[i + half]);
        float4 v0 = in4[e0.x * 16 + qlane];
        float w0 = __int_as_float(e0.y);
        a0.x = fmaf(w0, v0.x, a0.x); a0.y = fmaf(w0, v0.y, a0.y);
        a0.z = fmaf(w0, v0.z, a0.z); a0.w = fmaf(w0, v0.w, a0.w);
    }
    if (i + 2 + half < end) {
        int2 e1 = __ldcs(&g_edge[i + 2 + half]);
        float4 v1 = in4[e1.x * 16 + qlane];
        float w1 = __int_as_float(e1.y);
        a1.x = fmaf(w1, v1.x, a1.x); a1.y = fmaf(w1, v1.y, a1.y);
        a1.z = fmaf(w1, v1.z, a1.z); a1.w = fmaf(w1, v1.w, a1.w);
    }
    a0.x += a1.x; a0.y += a1.y; a0.z += a1.z; a0.w += a1.w;
    // combine halves: lane l and l^16 hold partial sums of the same columns
    a0.x += __shfl_xor_sync(0xFFFFFFFFu, a0.x, 16);
    a0.y += __shfl_xor_sync(0xFFFFFFFFu, a0.y, 16);
    a0.z += __shfl_xor_sync(0xFFFFFFFFu, a0.z, 16);
    a0.w += __shfl_xor_sync(0xFFFFFFFFu, a0.w, 16);
    if (half == 0) out4[w * 16 + qlane] = a0;
}

__global__ void k_gather1(const float* __restrict__ x) {
    gather_body(reinterpret_cast<const float4*>(x),
                reinterpret_cast<float4*>(g_tx1));
}

__global__ void k_gather2() {
    gather_body(reinterpret_cast<const float4*>(g_tx1),
                reinterpret_cast<float4*>(g_s2));
}

// ---------------- fused dense kernel: 128 nodes/group, 8 nodes/warp --------------
// H overlays the sTx region (freed after mainloop; sync before overlay writes).
#define SMEM_FLOATS (7 * 4096 + 192 + GROUP * 192)

__global__ void __launch_bounds__(512, 1)
k_final(const float* __restrict__ x, float* __restrict__ out) {
    extern __shared__ float sm[];
    float* sW  = sm;                   // 7*4096
    float* sB  = sW + 7 * 4096;       // 192
    float* sTx = sB + 192;            // GROUP nodes * (Tx0|Tx1|S2) * 64
    float* sH  = sTx;                 // overlay: GROUP*64 after mainloop

    const int tid = threadIdx.x;
    for (int i = tid; i < 7 * 4096; i += 512) sW[i] = g_wc[i];
    for (int i = tid; i < 192; i += 512) sB[i] = g_bias[i];

    const int warp = tid >> 5, lane = tid & 31;
    const int f = lane * 2;
    const int ngroups = (NN + GROUP - 1) / GROUP;

    for (int g = blockIdx.x; g < ngroups; g += gridDim.x) {
        const int base = g * GROUP;
        for (int i = tid; i < GROUP * 16; i += 512) {
            int node = i >> 4, q = i & 15;
            int n = base + node;
            float4 a, b, c;
            if (n < NN) {
                a = reinterpret_cast<const float4*>(x)[n * 16 + q];
                b = reinterpret_cast<const float4*>(g_tx1)[n * 16 + q];
                c = reinterpret_cast<const float4*>(g_s2)[n * 16 + q];
            } else {
                a = make_float4(0.f, 0.f, 0.f, 0.f); b = a; c = a;
            }
            reinterpret_cast<float4*>(sTx)[node * 48 + q]      = a;
            reinterpret_cast<float4*>(sTx)[node * 48 + 16 + q] = b;
            reinterpret_cast<float4*>(sTx)[node * 48 + 32 + q] = c;
        }
        __syncthreads();

        ull az[NPW], ah[NPW];
        {
            ull bz = *(const ull*)&sB[f];
            ull bh = *(const ull*)&sB[64 + f];
            #pragma unroll
            for (int j = 0; j < NPW; j++) { az[j] = bz; ah[j] = bh; }
        }
        const float* t = sTx + (warp * NPW) * 192;

        // mainloop: one activation matrix at a time per k4 block (bounded liveness)
        for (int k4 = 0; k4 < 64; k4 += 4) {
            #pragma unroll
            for (int m = 0; m < 3; m++) {
                ull wz[4], wh[4];
                #pragma unroll
                for (int kk = 0; kk < 4; kk++) {
                    wz[kk] = *(const ull*)&sW[m * 4096 + (k4 + kk) * 64 + f];
                    wh[kk] = *(const ull*)&sW[(m + 3) * 4096 + (k4 + kk) * 64 + f];
                }
                float4 Am[NPW];
                #pragma unroll
                for (int j = 0; j < NPW; j++)
                    Am[j] = *(const float4*)&t[j * 192 + m * 64 + k4];
                #pragma unroll
                for (int kk = 0; kk < 4; kk++) {
                    #pragma unroll
                    for (int j = 0; j < NPW; j++) {
                        const float* pa = (const float*)&Am[j];
                        ull a = dup2(pa[kk]);
                        fma2(az[j], a, wz[kk]);
                        fma2(ah[j], a, wh[kk]);
                    }
                }
            }
        }

        // gates into registers
        float Hx[NPW], Hy[NPW];
        #pragma unroll
        for (int j = 0; j < NPW; j++) {
            float azx, azy, ahx, ahy;
            unpk2(az[j], azx, azy);
            unpk2(ah[j], ahx, ahy);
            float zx = 1.f / (1.f + __expf(-azx));
            float zy = 1.f / (1.f + __expf(-azy));
            float hx = 1.f - 2.f / (__expf(2.f * ahx) + 1.f);
            float hy = 1.f - 2.f / (__expf(2.f * ahy) + 1.f);
            Hx[j] = fmaxf((1.f - zx) * hx, 0.f);
            Hy[j] = fmaxf((1.f - zy) * hy, 0.f);
        }
        __syncthreads();   // ALL warps done reading sTx before H overlay

        #pragma unroll
        for (int j = 0; j < NPW; j++) {
            int node = warp * NPW + j;
            sH[node * 64 + f]     = Hx[j];
            sH[node * 64 + f + 1] = Hy[j];
        }
        // each warp reads only its own nodes' H -> no sync needed

        ull o[NPW];
        {
            ull bl = *(const ull*)&sB[128 + f];
            #pragma unroll
            for (int j = 0; j < NPW; j++) o[j] = bl;
        }
        for (int k4 = 0; k4 < 64; k4 += 4) {
            ull wl[4];
            #pragma unroll
            for (int kk = 0; kk < 4; kk++)
                wl[kk] = *(const ull*)&sW[6 * 4096 + (k4 + kk) * 64 + f];
            float4 Hv[NPW];
            #pragma unroll
            for (int j = 0; j < NPW; j++)
                Hv[j] = *(const float4*)&sH[(warp * NPW + j) * 64 + k4];
            #pragma unroll
            for (int kk = 0; kk < 4; kk++) {
                #pragma unroll
                for (int j = 0; j < NPW; j++) {
                    const float* ph = (const float*)&Hv[j];
                    fma2(o[j], dup2(ph[kk]), wl[kk]);
                }
            }
        }
        #pragma unroll
        for (int j = 0; j < NPW; j++) {
            int n = base + warp * NPW + j;
            if (n < NN) {
                float ox, oy;
                unpk2(o[j], ox, oy);
                *(float2*)&out[n * 64 + f] = make_float2(ox, oy);
            }
        }
        __syncthreads();
    }

    // tail: restore zeroed state for the next invocation (replaces k_zero kernel)
    for (int i = blockIdx.x * 512 + tid; i < NN; i += gridDim.x * 512) {
        g_deg[i] = 0.f;
        g_cnt[i] = 0;
    }
    if (blockIdx.x == 0 && tid == 0) g_total = 0;
}

// ---------------- launch ----------------
extern "C" void kernel_launch(void* const* d_in, const int* in_sizes, int n_in,
                              void* d_out, int out_size) {
    const float* x    = (const float*)d_in[0];
    const int*   ei   = (const int*)d_in[1];
    const float* ew   = (const float*)d_in[2];
    const float* Wxz  = (const float*)d_in[3];
    const float* bxz  = (const float*)d_in[4];
    const float* bhz  = (const float*)d_in[6];   // W_hz unused (H0 = 0)
    const float* Wxh  = (const float*)d_in[11];
    const float* bxh  = (const float*)d_in[12];
    const float* bhh  = (const float*)d_in[14];  // W_hh unused
    const float* Wlin = (const float*)d_in[15];
    const float* blin = (const float*)d_in[16];
    float* out = (float*)d_out;

    const int* src = ei;
    const int* dst = ei + NE;

    cudaFuncSetAttribute(k_final, cudaFuncAttributeMaxDynamicSharedMemorySize,
                         SMEM_FLOATS * (int)sizeof(float));

    k_hist<<<(NE / 4 + 255) / 256, 256>>>(src, dst, ew);
    k_prep<<<(NN + 255) / 256, 256>>>(Wxz, bxz, bhz, Wxh, bxh, bhh, Wlin, blin);
    k_permute<<<(NE / 4 + 255) / 256, 256>>>(src, dst, ew);
    k_gather1<<<(NN * 32 + 255) / 256, 256>>>(x);
    k_gather2<<<(NN * 32 + 255) / 256, 256>>>();
    k_final<<<148, 512, SMEM_FLOATS * (int)sizeof(float)>>>(x, out);
}